// round 8
// baseline (speedup 1.0000x reference)
#include <cuda_runtime.h>
#include <cuda_bf16.h>
#include <math.h>
#include <stdint.h>

#define B_ 8
#define N_ 256
#define D_ 512
#define H_ 16
#define K_ 4
#define DK_ 32
#define FFN_ 2048
#define BN_ 2048   // B*N
#define KD_ 2048   // K*D

// ------------------- scratch (static device allocations) -------------------
__device__ __align__(256) float g_q[BN_ * D_];
__device__ __align__(256) float g_k[BN_ * D_];
__device__ __align__(256) float g_v[BN_ * D_];
__device__ __align__(256) float g_msg[BN_ * KD_];
__device__ __align__(256) float g_t1[BN_ * D_];
__device__ __align__(256) float g_t2[BN_ * D_];
__device__ __align__(256) float g_y[BN_ * D_];
__device__ __align__(256) float g_t3[BN_ * FFN_];
__device__ __align__(256) float g_t4[BN_ * D_];

// ------------------- helpers ----------------------------------------------
__device__ __forceinline__ uint32_t smem_u32(const void* p) {
    uint32_t a;
    asm("{ .reg .u64 t; cvta.to.shared.u64 t, %1; cvt.u32.u64 %0, t; }"
        : "=r"(a) : "l"(p));
    return a;
}

__device__ __forceinline__ void ldsm_x4(uint32_t& r0, uint32_t& r1,
                                        uint32_t& r2, uint32_t& r3, uint32_t a) {
    asm volatile("ldmatrix.sync.aligned.m8n8.x4.shared.b16 {%0,%1,%2,%3}, [%4];"
                 : "=r"(r0), "=r"(r1), "=r"(r2), "=r"(r3) : "r"(a));
}
__device__ __forceinline__ void ldsm_x4_t(uint32_t& r0, uint32_t& r1,
                                          uint32_t& r2, uint32_t& r3, uint32_t a) {
    asm volatile("ldmatrix.sync.aligned.m8n8.x4.trans.shared.b16 {%0,%1,%2,%3}, [%4];"
                 : "=r"(r0), "=r"(r1), "=r"(r2), "=r"(r3) : "r"(a));
}

__device__ __forceinline__ void mma_bf16(float* c, const uint32_t* a,
                                         const uint32_t* b) {
    asm volatile(
        "mma.sync.aligned.m16n8k16.row.col.f32.bf16.bf16.f32 "
        "{%0,%1,%2,%3}, {%4,%5,%6,%7}, {%8,%9}, {%0,%1,%2,%3};"
        : "+f"(c[0]), "+f"(c[1]), "+f"(c[2]), "+f"(c[3])
        : "r"(a[0]), "r"(a[1]), "r"(a[2]), "r"(a[3]), "r"(b[0]), "r"(b[1]));
}

// split a float into bf16 hi + bf16 lo; pack pairs (low element = low half)
__device__ __forceinline__ void split2(float x, float y, uint32_t& hi, uint32_t& lo) {
    __nv_bfloat16 hx = __float2bfloat16_rn(x);
    __nv_bfloat16 hy = __float2bfloat16_rn(y);
    __nv_bfloat16 lx = __float2bfloat16_rn(x - __bfloat162float(hx));
    __nv_bfloat16 ly = __float2bfloat16_rn(y - __bfloat162float(hy));
    __nv_bfloat162 h2 = __nv_bfloat162(hx, hy);
    __nv_bfloat162 l2 = __nv_bfloat162(lx, ly);
    hi = *(uint32_t*)&h2;
    lo = *(uint32_t*)&l2;
}

// ------------------- bf16x3 tensor-core GEMM (double buffered) -------------
// C[M,Nc] = act(A[M,Kc] @ W[Kc,Nc] + bias). Tile 64(M) x 64(N), K-chunk 32.
// 3-term split: D += Ah*Bh + Ah*Bl + Al*Bh (bf16 mma, fp32 accum).
// 8 warps = 4(M) x 2(N); warp tile 16x32. 2 CTAs/SM.
// A smem [m][k] pitch 40 bf16 (80B rows -> conflict-free LDSM).
// B smem [k][n] pitch 72 bf16 (144B rows), read via ldmatrix.x4.trans.
// Double-buffered: STS(c+1) + LDG(c+2) issue alongside MMA(c); 1 sync/chunk.
#define A_PITCH 40
#define B_PITCH 72
// byte offsets inside one buffer
#define SA_HI 0
#define SA_LO 5120            // 64*40*2
#define SB_HI 10240
#define SB_LO 14848           // +32*72*2
#define BUF_BYTES 19456
#define GEMM_SMEM (2 * BUF_BYTES)   // 38912

template <int ACT>
__device__ __forceinline__ void tc_gemm_body(
    const float* __restrict__ A, const float* __restrict__ W,
    const float* __restrict__ bias, float* __restrict__ C,
    int Nc, int Kc)
{
    extern __shared__ __align__(16) char smem[];
    uint32_t uS = smem_u32(smem);

    int tid = threadIdx.x;
    int lane = tid & 31;
    int warp = tid >> 5;
    int warpM = warp & 3;        // m offset 0,16,32,48
    int warpN = warp >> 2;       // n offset 0,32
    int rowBase = blockIdx.y * 64;
    int colBase = blockIdx.x * 64;

    // fill slices: A chunk 64x32 fp32 = 512 float4 (2/thread)
    int am = tid >> 3;                 // 0..31 (second at +32)
    int ak = (tid & 7) * 4;
    const float* Aptr = A + (size_t)(rowBase + am) * Kc + ak;
    // B chunk 32x64 fp32 = 512 float4 (2/thread)
    int bk = tid >> 4;                 // 0..15 (second at +16)
    int bn = (tid & 15) * 4;
    const float* Wptr = W + (size_t)bk * Nc + colBase + bn;

    float acc[4][4];
#pragma unroll
    for (int nb = 0; nb < 4; nb++)
#pragma unroll
        for (int j = 0; j < 4; j++) acc[nb][j] = 0.f;

    // LDSM base addresses (buffer-relative byte offsets)
    uint32_t aRow = (uint32_t)(warpM * 16 + (lane & 15)) * (A_PITCH * 2)
                    + ((lane >> 4) << 4);
    uint32_t bRow = (uint32_t)(lane & 15) * (B_PITCH * 2)
                    + (uint32_t)(warpN * 32) * 2 + ((lane >> 4) << 4);

    float4 pa[2], pb[2];

    // STS helper via lambda-free macro-ish inline
    auto sts_chunk = [&](uint32_t base) {
#pragma unroll
        for (int it = 0; it < 2; it++) {
            uint32_t off = (uint32_t)((am + it * 32) * A_PITCH + ak) * 2;
            uint32_t h0, l0, h1, l1;
            split2(pa[it].x, pa[it].y, h0, l0);
            split2(pa[it].z, pa[it].w, h1, l1);
            *(uint2*)(smem + (base + SA_HI + off)) = make_uint2(h0, h1);
            *(uint2*)(smem + (base + SA_LO + off)) = make_uint2(l0, l1);
        }
#pragma unroll
        for (int it = 0; it < 2; it++) {
            uint32_t off = (uint32_t)((bk + it * 16) * B_PITCH + bn) * 2;
            uint32_t h0, l0, h1, l1;
            split2(pb[it].x, pb[it].y, h0, l0);
            split2(pb[it].z, pb[it].w, h1, l1);
            *(uint2*)(smem + (base + SB_HI + off)) = make_uint2(h0, h1);
            *(uint2*)(smem + (base + SB_LO + off)) = make_uint2(l0, l1);
        }
    };
    auto ldg_chunk = [&](int c) {
        const float* An = Aptr + c * 32;
        const float* Wn = Wptr + (size_t)(c * 32) * Nc;
#pragma unroll
        for (int it = 0; it < 2; it++)
            pa[it] = *(const float4*)(An + (size_t)(it * 32) * Kc);
#pragma unroll
        for (int it = 0; it < 2; it++)
            pb[it] = *(const float4*)(Wn + (size_t)(it * 16) * Nc);
    };

    int nch = Kc >> 5;

    // prologue
    ldg_chunk(0);
    sts_chunk(0);
    __syncthreads();
    ldg_chunk(1);          // nch >= 16 always

    for (int c = 0; c < nch; c++) {
        int bf = c & 1;
        uint32_t cur = (uint32_t)(bf * BUF_BYTES);
        uint32_t nxt = (uint32_t)((bf ^ 1) * BUF_BYTES);

        // stage next chunk into the other buffer while MMAs run on this one
        if (c + 1 < nch) sts_chunk(nxt);
        if (c + 2 < nch) ldg_chunk(c + 2);

#pragma unroll
        for (int ks = 0; ks < 2; ks++) {
            uint32_t ah[4], al[4];
            uint32_t aoff = cur + aRow + ks * 32;
            ldsm_x4(ah[0], ah[1], ah[2], ah[3], uS + SA_HI + aoff);
            ldsm_x4(al[0], al[1], al[2], al[3], uS + SA_LO + aoff);
            uint32_t bh[4][2], bl[4][2];
#pragma unroll
            for (int nbp = 0; nbp < 2; nbp++) {
                uint32_t boff = cur + bRow + (uint32_t)(ks * 16) * (B_PITCH * 2)
                                + (uint32_t)(nbp * 16) * 2;
                ldsm_x4_t(bh[nbp * 2][0], bh[nbp * 2][1],
                          bh[nbp * 2 + 1][0], bh[nbp * 2 + 1][1], uS + SB_HI + boff);
                ldsm_x4_t(bl[nbp * 2][0], bl[nbp * 2][1],
                          bl[nbp * 2 + 1][0], bl[nbp * 2 + 1][1], uS + SB_LO + boff);
            }
#pragma unroll
            for (int nb = 0; nb < 4; nb++) {
                mma_bf16(acc[nb], ah, bh[nb]);
                mma_bf16(acc[nb], ah, bl[nb]);
                mma_bf16(acc[nb], al, bh[nb]);
            }
        }
        __syncthreads();
    }

    // ---- epilogue: bias + activation + float2 stores ----
    int r0 = rowBase + warpM * 16 + (lane >> 2);
#pragma unroll
    for (int nb = 0; nb < 4; nb++) {
        int col = colBase + warpN * 32 + nb * 8 + (lane & 3) * 2;
        float b0 = bias[col], b1 = bias[col + 1];
#pragma unroll
        for (int half = 0; half < 2; half++) {
            int r = r0 + half * 8;
            float v0 = acc[nb][half * 2 + 0] + b0;
            float v1 = acc[nb][half * 2 + 1] + b1;
            if (ACT == 1) {                       // SiLU
                v0 = v0 / (1.f + __expf(-v0));
                v1 = v1 / (1.f + __expf(-v1));
            } else if (ACT == 2) {                // exact GELU
                v0 = 0.5f * v0 * (1.f + erff(v0 * 0.70710678118654752f));
                v1 = 0.5f * v1 * (1.f + erff(v1 * 0.70710678118654752f));
            }
            *(float2*)&C[(size_t)r * Nc + col] = make_float2(v0, v1);
        }
    }
}

template <int ACT>
__global__ __launch_bounds__(256, 2) void tc_gemm(
    const float* __restrict__ A, const float* __restrict__ W,
    const float* __restrict__ bias, float* __restrict__ C,
    int Nc, int Kc)
{
    tc_gemm_body<ACT>(A, W, bias, C, Nc, Kc);
}

// fused Q/K/V projection: blockIdx.z picks the weight/out triple
__global__ __launch_bounds__(256, 2) void tc_qkv(
    const float* __restrict__ x,
    const float* __restrict__ Wq, const float* __restrict__ bq,
    const float* __restrict__ Wk, const float* __restrict__ bk,
    const float* __restrict__ Wv, const float* __restrict__ bv,
    float* __restrict__ q, float* __restrict__ k, float* __restrict__ v)
{
    int z = blockIdx.z;
    const float* W  = (z == 0) ? Wq : ((z == 1) ? Wk : Wv);
    const float* bb = (z == 0) ? bq : ((z == 1) ? bk : bv);
    float* C        = (z == 0) ? q  : ((z == 1) ? k  : v);
    tc_gemm_body<0>(x, W, bb, C, D_, D_);
}

// ------------------- fused multi-scale attention ---------------------------
// grid (B*H, 4): block = one (b,h) and a 64-query chunk. 101KB smem -> 2 CTAs/SM.
__global__ __launch_bounds__(256, 2) void attn_kernel(
    const float* __restrict__ qb, const float* __restrict__ kb,
    const float* __restrict__ vb, const float* __restrict__ attn_bias,
    const int* __restrict__ mask, const float* __restrict__ dist,
    const float* __restrict__ dist_bar, float* __restrict__ msg)
{
    extern __shared__ float sm[];
    float* Ks = sm;                  // 256*33
    float* Vs = Ks + 256 * 33;       // 256*33
    float* Ps = Vs + 256 * 33;       // 8 warps * 256*4
    float* Qs = Ps + 8 * 1024;       // 8 warps * 32

    int bh = blockIdx.x;
    int b = bh >> 4;
    int h = bh & 15;
    int qbase = blockIdx.y * 64;
    int tid = threadIdx.x;
    int lane = tid & 31;
    int warp = tid >> 5;

    float bar[4];
#pragma unroll
    for (int k = 0; k < 4; k++) bar[k] = dist_bar[k];

    for (int idx = tid; idx < 256 * 8; idx += 256) {
        int m = idx >> 3;
        int dq = (idx & 7) * 4;
        size_t gi = (size_t)(b * 256 + m) * 512 + h * 32 + dq;
        float4 k4 = *(const float4*)&kb[gi];
        float4 v4 = *(const float4*)&vb[gi];
        Ks[m * 33 + dq + 0] = k4.x; Ks[m * 33 + dq + 1] = k4.y;
        Ks[m * 33 + dq + 2] = k4.z; Ks[m * 33 + dq + 3] = k4.w;
        Vs[m * 33 + dq + 0] = v4.x; Vs[m * 33 + dq + 1] = v4.y;
        Vs[m * 33 + dq + 2] = v4.z; Vs[m * 33 + dq + 3] = v4.w;
    }
    __syncthreads();

    float* Pw = Ps + warp * 1024;
    float* Qw = Qs + warp * 32;
    const float scl = 0.17677669529663687f; // 1/sqrt(32)

    for (int n = qbase + warp; n < qbase + 64; n += 8) {
        Qw[lane] = qb[(size_t)(b * 256 + n) * 512 + h * 32 + lane];
        __syncwarp();

        unsigned pmbits = 0;
        float nd[8];
        float bias_r[4][8];
        {
            const float* bp = attn_bias + ((size_t)(b * 4) * 256 + n) * 256 + lane;
#pragma unroll
            for (int j = 0; j < 8; j++) {
                int m = lane + 32 * j;
                if (mask[(size_t)(b * 256 + n) * 256 + m] != 0) pmbits |= (1u << j);
                nd[j] = (n == 0 || m == 0) ? 0.f
                                           : dist[(size_t)(b * 255 + (n - 1)) * 255 + (m - 1)];
#pragma unroll
                for (int k = 0; k < 4; k++)
                    bias_r[k][j] = bp[(size_t)k * 65536 + 32 * j];
            }
        }

        float s[8];
#pragma unroll
        for (int j = 0; j < 8; j++) s[j] = 0.f;
#pragma unroll
        for (int d = 0; d < 32; d++) {
            float qv = Qw[d];
#pragma unroll
            for (int j = 0; j < 8; j++) s[j] += qv * Ks[(lane + 32 * j) * 33 + d];
        }
#pragma unroll
        for (int j = 0; j < 8; j++) s[j] *= scl;

#pragma unroll
        for (int k = 0; k < 4; k++) {
            float sc[8];
            float mx = -3.4e38f;
#pragma unroll
            for (int j = 0; j < 8; j++) {
                int m = lane + 32 * j;
                bool within = (nd[j] < bar[k]) || (n == 0) || (m == 0);
                bool ok = ((pmbits >> j) & 1u) && within;
                sc[j] = ok ? (s[j] + bias_r[k][j]) : -1e12f;
                mx = fmaxf(mx, sc[j]);
            }
#pragma unroll
            for (int o = 16; o > 0; o >>= 1)
                mx = fmaxf(mx, __shfl_xor_sync(0xffffffffu, mx, o));
            float sum = 0.f;
#pragma unroll
            for (int j = 0; j < 8; j++) {
                sc[j] = __expf(sc[j] - mx);
                sum += sc[j];
            }
#pragma unroll
            for (int o = 16; o > 0; o >>= 1)
                sum += __shfl_xor_sync(0xffffffffu, sum, o);
            float inv = 1.f / sum;
#pragma unroll
            for (int j = 0; j < 8; j++)
                Pw[(lane + 32 * j) * 4 + k] = sc[j] * inv;
        }
        __syncwarp();

        float a0 = 0.f, a1 = 0.f, a2 = 0.f, a3 = 0.f;
        const float* pw = Pw;
        const float* vp = Vs + lane;
#pragma unroll 8
        for (int m = 0; m < 256; m++) {
            float4 pv = *(const float4*)pw;
            float v = *vp;
            a0 += pv.x * v;
            a1 += pv.y * v;
            a2 += pv.z * v;
            a3 += pv.w * v;
            pw += 4;
            vp += 33;
        }

        int d = lane;
        int c = (d & 7) * 256 + n;
        float av[4] = {a0, a1, a2, a3};
#pragma unroll
        for (int k = 0; k < 4; k++) {
            int npr = (k * 16 + h) * 4 + (d >> 3);
            msg[(size_t)(b * 256 + npr) * 2048 + c] = av[k];
        }
        __syncwarp();
    }
}

// ------------------- fused residual + LayerNorm ----------------------------
__global__ __launch_bounds__(256) void add_ln_kernel(
    const float* __restrict__ a, const float* __restrict__ r,
    const float* __restrict__ g, const float* __restrict__ be,
    float* __restrict__ out)
{
    int row = blockIdx.x;
    int tid = threadIdx.x;
    int lane = tid & 31;
    int warp = tid >> 5;

    const float* ar = a + (size_t)row * 512;
    const float* rr = r + (size_t)row * 512;
    float v0 = ar[tid] + rr[tid];
    float v1 = ar[tid + 256] + rr[tid + 256];

    __shared__ float red[8];
    __shared__ float sMean, sRstd;

    float s = v0 + v1;
#pragma unroll
    for (int o = 16; o > 0; o >>= 1) s += __shfl_xor_sync(0xffffffffu, s, o);
    if (lane == 0) red[warp] = s;
    __syncthreads();
    if (tid == 0) {
        float t = 0.f;
#pragma unroll
        for (int i = 0; i < 8; i++) t += red[i];
        sMean = t * (1.f / 512.f);
    }
    __syncthreads();
    float mean = sMean;
    float d0 = v0 - mean;
    float d1 = v1 - mean;
    float q = d0 * d0 + d1 * d1;
#pragma unroll
    for (int o = 16; o > 0; o >>= 1) q += __shfl_xor_sync(0xffffffffu, q, o);
    if (lane == 0) red[warp] = q;
    __syncthreads();
    if (tid == 0) {
        float t = 0.f;
#pragma unroll
        for (int i = 0; i < 8; i++) t += red[i];
        sRstd = rsqrtf(t * (1.f / 512.f) + 1e-6f);
    }
    __syncthreads();
    float rstd = sRstd;
    out[(size_t)row * 512 + tid] = d0 * rstd * g[tid] + be[tid];
    out[(size_t)row * 512 + tid + 256] = d1 * rstd * g[tid + 256] + be[tid + 256];
}

// ------------------- launch ------------------------------------------------
extern "C" void kernel_launch(void* const* d_in, const int* in_sizes, int n_in,
                              void* d_out, int out_size)
{
    int base = (n_in >= 24) ? 6 : 5;

    const float* x         = (const float*)d_in[0];
    const float* dist      = (const float*)d_in[1];
    const float* dist_bar  = (const float*)d_in[2];
    const float* attn_bias = (const float*)d_in[3];
    const int*   mask      = (const int*)d_in[4];
    const float* Wq  = (const float*)d_in[base + 0];
    const float* bq  = (const float*)d_in[base + 1];
    const float* Wk  = (const float*)d_in[base + 2];
    const float* bk  = (const float*)d_in[base + 3];
    const float* Wv  = (const float*)d_in[base + 4];
    const float* bv  = (const float*)d_in[base + 5];
    const float* W1  = (const float*)d_in[base + 6];
    const float* b1  = (const float*)d_in[base + 7];
    const float* W2  = (const float*)d_in[base + 8];
    const float* b2  = (const float*)d_in[base + 9];
    const float* g1  = (const float*)d_in[base + 10];
    const float* be1 = (const float*)d_in[base + 11];
    const float* Wf1 = (const float*)d_in[base + 12];
    const float* bf1 = (const float*)d_in[base + 13];
    const float* Wf2 = (const float*)d_in[base + 14];
    const float* bf2 = (const float*)d_in[base + 15];
    const float* g2  = (const float*)d_in[base + 16];
    const float* be2 = (const float*)d_in[base + 17];
    float* out = (float*)d_out;

    float *qb, *kb, *vb, *msgb, *t1, *t2, *yb, *t3, *t4;
    cudaGetSymbolAddress((void**)&qb, g_q);
    cudaGetSymbolAddress((void**)&kb, g_k);
    cudaGetSymbolAddress((void**)&vb, g_v);
    cudaGetSymbolAddress((void**)&msgb, g_msg);
    cudaGetSymbolAddress((void**)&t1, g_t1);
    cudaGetSymbolAddress((void**)&t2, g_t2);
    cudaGetSymbolAddress((void**)&yb, g_y);
    cudaGetSymbolAddress((void**)&t3, g_t3);
    cudaGetSymbolAddress((void**)&t4, g_t4);

    const int ATTN_SMEM = (256 * 33 * 2 + 8 * 1024 + 8 * 32) * 4; // 101376 B
    cudaFuncSetAttribute(attn_kernel,
                         cudaFuncAttributeMaxDynamicSharedMemorySize, ATTN_SMEM);
    cudaFuncSetAttribute(tc_gemm<0>,
                         cudaFuncAttributeMaxDynamicSharedMemorySize, GEMM_SMEM);
    cudaFuncSetAttribute(tc_gemm<1>,
                         cudaFuncAttributeMaxDynamicSharedMemorySize, GEMM_SMEM);
    cudaFuncSetAttribute(tc_gemm<2>,
                         cudaFuncAttributeMaxDynamicSharedMemorySize, GEMM_SMEM);
    cudaFuncSetAttribute(tc_qkv,
                         cudaFuncAttributeMaxDynamicSharedMemorySize, GEMM_SMEM);

    dim3 blk(256);
    dim3 gQKV(D_ / 64, BN_ / 64, 3);     // 8 x 32 x 3
    dim3 gD(D_ / 64, BN_ / 64);          // 8 x 32 = 256
    dim3 gF(FFN_ / 64, BN_ / 64);        // 32 x 32 = 1024
    dim3 gAttn(B_ * H_, 4);              // 512 blocks

    // QKV projections (tensor cores, z picks W)
    tc_qkv<<<gQKV, blk, GEMM_SMEM>>>(x, Wq, bq, Wk, bk, Wv, bv, qb, kb, vb);

    // fused multi-scale attention + torch-reshape scatter
    attn_kernel<<<gAttn, blk, ATTN_SMEM>>>(qb, kb, vb, attn_bias, mask,
                                           dist, dist_bar, msgb);

    // MLP: silu(msg @ W1 + b1) @ W2 + b2 ; y = LN(h + x)
    tc_gemm<1><<<gD, blk, GEMM_SMEM>>>(msgb, W1, b1, t1, D_, KD_);
    tc_gemm<0><<<gD, blk, GEMM_SMEM>>>(t1, W2, b2, t2, D_, D_);
    add_ln_kernel<<<BN_, blk>>>(t2, x, g1, be1, yb);

    // FFN: gelu(y @ Wf1 + bf1) @ Wf2 + bf2 ; out = LN(f + y)
    tc_gemm<2><<<gF, blk, GEMM_SMEM>>>(yb, Wf1, bf1, t3, FFN_, D_);
    tc_gemm<0><<<gD, blk, GEMM_SMEM>>>(t3, Wf2, bf2, t4, D_, FFN_);
    add_ln_kernel<<<BN_, blk>>>(t4, yb, g2, be2, out);
}

// round 11
// speedup vs baseline: 1.2360x; 1.2360x over previous
#include <cuda_runtime.h>
#include <cuda_bf16.h>
#include <math.h>
#include <stdint.h>

#define B_ 8
#define N_ 256
#define D_ 512
#define H_ 16
#define K_ 4
#define DK_ 32
#define FFN_ 2048
#define BN_ 2048   // B*N
#define KD_ 2048   // K*D

// ------------------- scratch (static device allocations) -------------------
__device__ __align__(256) float g_q[BN_ * D_];
__device__ __align__(256) float g_k[BN_ * D_];
__device__ __align__(256) float g_v[BN_ * D_];
__device__ __align__(256) float g_msg[BN_ * KD_];
__device__ __align__(256) float g_t1[BN_ * D_];
__device__ __align__(256) float g_t2[BN_ * D_];
__device__ __align__(256) float g_y[BN_ * D_];
__device__ __align__(256) float g_t3[BN_ * FFN_];
__device__ __align__(256) float g_t4[BN_ * D_];

// ------------------- helpers ----------------------------------------------
__device__ __forceinline__ uint32_t smem_u32(const void* p) {
    uint32_t a;
    asm("{ .reg .u64 t; cvta.to.shared.u64 t, %1; cvt.u32.u64 %0, t; }"
        : "=r"(a) : "l"(p));
    return a;
}

__device__ __forceinline__ void ldsm_x4(uint32_t& r0, uint32_t& r1,
                                        uint32_t& r2, uint32_t& r3, uint32_t a) {
    asm volatile("ldmatrix.sync.aligned.m8n8.x4.shared.b16 {%0,%1,%2,%3}, [%4];"
                 : "=r"(r0), "=r"(r1), "=r"(r2), "=r"(r3) : "r"(a));
}
__device__ __forceinline__ void ldsm_x4_t(uint32_t& r0, uint32_t& r1,
                                          uint32_t& r2, uint32_t& r3, uint32_t a) {
    asm volatile("ldmatrix.sync.aligned.m8n8.x4.trans.shared.b16 {%0,%1,%2,%3}, [%4];"
                 : "=r"(r0), "=r"(r1), "=r"(r2), "=r"(r3) : "r"(a));
}

__device__ __forceinline__ void mma_bf16(float* c, const uint32_t* a,
                                         const uint32_t* b) {
    asm volatile(
        "mma.sync.aligned.m16n8k16.row.col.f32.bf16.bf16.f32 "
        "{%0,%1,%2,%3}, {%4,%5,%6,%7}, {%8,%9}, {%0,%1,%2,%3};"
        : "+f"(c[0]), "+f"(c[1]), "+f"(c[2]), "+f"(c[3])
        : "r"(a[0]), "r"(a[1]), "r"(a[2]), "r"(a[3]), "r"(b[0]), "r"(b[1]));
}

// split a float into bf16 hi + bf16 lo; pack pairs (low element = low half)
__device__ __forceinline__ void split2(float x, float y, uint32_t& hi, uint32_t& lo) {
    __nv_bfloat16 hx = __float2bfloat16_rn(x);
    __nv_bfloat16 hy = __float2bfloat16_rn(y);
    __nv_bfloat16 lx = __float2bfloat16_rn(x - __bfloat162float(hx));
    __nv_bfloat16 ly = __float2bfloat16_rn(y - __bfloat162float(hy));
    __nv_bfloat162 h2 = __nv_bfloat162(hx, hy);
    __nv_bfloat162 l2 = __nv_bfloat162(lx, ly);
    hi = *(uint32_t*)&h2;
    lo = *(uint32_t*)&l2;
}

// ------------------- bf16x3 tensor-core GEMM (double buffered) -------------
// (unchanged from the passing R8 kernel)
#define A_PITCH 40
#define B_PITCH 72
#define SA_HI 0
#define SA_LO 5120
#define SB_HI 10240
#define SB_LO 14848
#define BUF_BYTES 19456
#define GEMM_SMEM (2 * BUF_BYTES)

template <int ACT>
__device__ __forceinline__ void tc_gemm_body(
    const float* __restrict__ A, const float* __restrict__ W,
    const float* __restrict__ bias, float* __restrict__ C,
    int Nc, int Kc)
{
    extern __shared__ __align__(16) char smem[];
    uint32_t uS = smem_u32(smem);

    int tid = threadIdx.x;
    int lane = tid & 31;
    int warp = tid >> 5;
    int warpM = warp & 3;
    int warpN = warp >> 2;
    int rowBase = blockIdx.y * 64;
    int colBase = blockIdx.x * 64;

    int am = tid >> 3;
    int ak = (tid & 7) * 4;
    const float* Aptr = A + (size_t)(rowBase + am) * Kc + ak;
    int bk = tid >> 4;
    int bn = (tid & 15) * 4;
    const float* Wptr = W + (size_t)bk * Nc + colBase + bn;

    float acc[4][4];
#pragma unroll
    for (int nb = 0; nb < 4; nb++)
#pragma unroll
        for (int j = 0; j < 4; j++) acc[nb][j] = 0.f;

    uint32_t aRow = (uint32_t)(warpM * 16 + (lane & 15)) * (A_PITCH * 2)
                    + ((lane >> 4) << 4);
    uint32_t bRow = (uint32_t)(lane & 15) * (B_PITCH * 2)
                    + (uint32_t)(warpN * 32) * 2 + ((lane >> 4) << 4);

    float4 pa[2], pb[2];

    auto sts_chunk = [&](uint32_t base) {
#pragma unroll
        for (int it = 0; it < 2; it++) {
            uint32_t off = (uint32_t)((am + it * 32) * A_PITCH + ak) * 2;
            uint32_t h0, l0, h1, l1;
            split2(pa[it].x, pa[it].y, h0, l0);
            split2(pa[it].z, pa[it].w, h1, l1);
            *(uint2*)(smem + (base + SA_HI + off)) = make_uint2(h0, h1);
            *(uint2*)(smem + (base + SA_LO + off)) = make_uint2(l0, l1);
        }
#pragma unroll
        for (int it = 0; it < 2; it++) {
            uint32_t off = (uint32_t)((bk + it * 16) * B_PITCH + bn) * 2;
            uint32_t h0, l0, h1, l1;
            split2(pb[it].x, pb[it].y, h0, l0);
            split2(pb[it].z, pb[it].w, h1, l1);
            *(uint2*)(smem + (base + SB_HI + off)) = make_uint2(h0, h1);
            *(uint2*)(smem + (base + SB_LO + off)) = make_uint2(l0, l1);
        }
    };
    auto ldg_chunk = [&](int c) {
        const float* An = Aptr + c * 32;
        const float* Wn = Wptr + (size_t)(c * 32) * Nc;
#pragma unroll
        for (int it = 0; it < 2; it++)
            pa[it] = *(const float4*)(An + (size_t)(it * 32) * Kc);
#pragma unroll
        for (int it = 0; it < 2; it++)
            pb[it] = *(const float4*)(Wn + (size_t)(it * 16) * Nc);
    };

    int nch = Kc >> 5;
    ldg_chunk(0);
    sts_chunk(0);
    __syncthreads();
    ldg_chunk(1);

    for (int c = 0; c < nch; c++) {
        int bf = c & 1;
        uint32_t cur = (uint32_t)(bf * BUF_BYTES);
        uint32_t nxt = (uint32_t)((bf ^ 1) * BUF_BYTES);

        if (c + 1 < nch) sts_chunk(nxt);
        if (c + 2 < nch) ldg_chunk(c + 2);

#pragma unroll
        for (int ks = 0; ks < 2; ks++) {
            uint32_t ah[4], al[4];
            uint32_t aoff = cur + aRow + ks * 32;
            ldsm_x4(ah[0], ah[1], ah[2], ah[3], uS + SA_HI + aoff);
            ldsm_x4(al[0], al[1], al[2], al[3], uS + SA_LO + aoff);
            uint32_t bh[4][2], bl[4][2];
#pragma unroll
            for (int nbp = 0; nbp < 2; nbp++) {
                uint32_t boff = cur + bRow + (uint32_t)(ks * 16) * (B_PITCH * 2)
                                + (uint32_t)(nbp * 16) * 2;
                ldsm_x4_t(bh[nbp * 2][0], bh[nbp * 2][1],
                          bh[nbp * 2 + 1][0], bh[nbp * 2 + 1][1], uS + SB_HI + boff);
                ldsm_x4_t(bl[nbp * 2][0], bl[nbp * 2][1],
                          bl[nbp * 2 + 1][0], bl[nbp * 2 + 1][1], uS + SB_LO + boff);
            }
#pragma unroll
            for (int nb = 0; nb < 4; nb++) {
                mma_bf16(acc[nb], ah, bh[nb]);
                mma_bf16(acc[nb], ah, bl[nb]);
                mma_bf16(acc[nb], al, bh[nb]);
            }
        }
        __syncthreads();
    }

    int r0 = rowBase + warpM * 16 + (lane >> 2);
#pragma unroll
    for (int nb = 0; nb < 4; nb++) {
        int col = colBase + warpN * 32 + nb * 8 + (lane & 3) * 2;
        float b0 = bias[col], b1 = bias[col + 1];
#pragma unroll
        for (int half = 0; half < 2; half++) {
            int r = r0 + half * 8;
            float v0 = acc[nb][half * 2 + 0] + b0;
            float v1 = acc[nb][half * 2 + 1] + b1;
            if (ACT == 1) {
                v0 = v0 / (1.f + __expf(-v0));
                v1 = v1 / (1.f + __expf(-v1));
            } else if (ACT == 2) {
                v0 = 0.5f * v0 * (1.f + erff(v0 * 0.70710678118654752f));
                v1 = 0.5f * v1 * (1.f + erff(v1 * 0.70710678118654752f));
            }
            *(float2*)&C[(size_t)r * Nc + col] = make_float2(v0, v1);
        }
    }
}

template <int ACT>
__global__ __launch_bounds__(256, 2) void tc_gemm(
    const float* __restrict__ A, const float* __restrict__ W,
    const float* __restrict__ bias, float* __restrict__ C,
    int Nc, int Kc)
{
    tc_gemm_body<ACT>(A, W, bias, C, Nc, Kc);
}

__global__ __launch_bounds__(256, 2) void tc_qkv(
    const float* __restrict__ x,
    const float* __restrict__ Wq, const float* __restrict__ bq,
    const float* __restrict__ Wk, const float* __restrict__ bk,
    const float* __restrict__ Wv, const float* __restrict__ bv,
    float* __restrict__ q, float* __restrict__ k, float* __restrict__ v)
{
    int z = blockIdx.z;
    const float* W  = (z == 0) ? Wq : ((z == 1) ? Wk : Wv);
    const float* bb = (z == 0) ? bq : ((z == 1) ? bk : bv);
    float* C        = (z == 0) ? q  : ((z == 1) ? k  : v);
    tc_gemm_body<0>(x, W, bb, C, D_, D_);
}

// ------------------- MMA flash-style multi-scale attention -----------------
// Block = (b, h, 64-query chunk). 256 threads / 8 warps.
// S phase: warp = 16 q-rows x 128 keys, bf16x3 mma. Per scale: fragment
// softmax (cross-warp row reduce via smem), unnormalized e -> smem bf16
// hi/lo, then O_k += P.V via bf16x3 mma; 1/rowsum folded into epilogue.
#define AT_KPITCH 40
#define AT_PPITCH 264
#define AT_KH 0
#define AT_KL 20480
#define AT_VH 40960
#define AT_VL 61440
#define AT_QH 81920
#define AT_QL 87040
#define AT_PH 92160
#define AT_PL 125952
#define AT_STAT 159744       // float[2][64] rowmax staging
#define AT_RSUM 160256       // float[4][2][64] row sums
#define ATTN_SMEM 162304

__global__ __launch_bounds__(256, 1) void attn_mma_kernel(
    const float* __restrict__ qb, const float* __restrict__ kb,
    const float* __restrict__ vb, const float* __restrict__ attn_bias,
    const int* __restrict__ mask, const float* __restrict__ dist,
    const float* __restrict__ dist_bar, float* __restrict__ msg)
{
    extern __shared__ __align__(16) char smem[];
    uint32_t uS = smem_u32(smem);
    float* statf = (float*)(smem + AT_STAT);
    float* rsumf = (float*)(smem + AT_RSUM);

    int tid = threadIdx.x;
    int lane = tid & 31;
    int warp = tid >> 5;
    int b = blockIdx.x >> 4;
    int h = blockIdx.x & 15;
    int qbase = blockIdx.y * 64;
    int band = (warp & 3) * 16;      // q-row band (S + PV phases)
    int nhalf = (warp >> 2) * 128;   // key half (S phase)
    const float scl = 0.17677669529663687f;  // 1/sqrt(32)

    float bar[4];
#pragma unroll
    for (int k = 0; k < 4; k++) bar[k] = dist_bar[k];

    // ---- fill K,V (256x32) and Q (64x32, pre-scaled), split bf16 hi/lo ----
    for (int idx = tid; idx < 2048; idx += 256) {
        int key = idx >> 3;
        int dq = (idx & 7) * 4;
        size_t gi = (size_t)(b * 256 + key) * 512 + h * 32 + dq;
        float4 k4 = *(const float4*)&kb[gi];
        float4 v4 = *(const float4*)&vb[gi];
        uint32_t off = (uint32_t)(key * AT_KPITCH + dq) * 2;
        uint32_t h0, l0, h1, l1;
        split2(k4.x, k4.y, h0, l0); split2(k4.z, k4.w, h1, l1);
        *(uint2*)(smem + AT_KH + off) = make_uint2(h0, h1);
        *(uint2*)(smem + AT_KL + off) = make_uint2(l0, l1);
        split2(v4.x, v4.y, h0, l0); split2(v4.z, v4.w, h1, l1);
        *(uint2*)(smem + AT_VH + off) = make_uint2(h0, h1);
        *(uint2*)(smem + AT_VL + off) = make_uint2(l0, l1);
    }
    for (int idx = tid; idx < 512; idx += 256) {
        int r = idx >> 3;
        int dq = (idx & 7) * 4;
        size_t gi = (size_t)(b * 256 + qbase + r) * 512 + h * 32 + dq;
        float4 q4 = *(const float4*)&qb[gi];
        q4.x *= scl; q4.y *= scl; q4.z *= scl; q4.w *= scl;
        uint32_t off = (uint32_t)(r * AT_KPITCH + dq) * 2;
        uint32_t h0, l0, h1, l1;
        split2(q4.x, q4.y, h0, l0); split2(q4.z, q4.w, h1, l1);
        *(uint2*)(smem + AT_QH + off) = make_uint2(h0, h1);
        *(uint2*)(smem + AT_QL + off) = make_uint2(l0, l1);
    }
    __syncthreads();

    // ---- S = Q.K^T (bf16x3), warp tile 16 x 128 -> 16 n8-frag tiles -------
    float sacc[16][4];
#pragma unroll
    for (int t = 0; t < 16; t++)
#pragma unroll
        for (int j = 0; j < 4; j++) sacc[t][j] = 0.f;

#pragma unroll
    for (int ks = 0; ks < 2; ks++) {
        uint32_t qh4[4], ql4[4];
        uint32_t aoff = (uint32_t)((band + (lane & 15)) * AT_KPITCH + ks * 16) * 2
                        + ((lane >> 4) << 4);
        ldsm_x4(qh4[0], qh4[1], qh4[2], qh4[3], uS + AT_QH + aoff);
        ldsm_x4(ql4[0], ql4[1], ql4[2], ql4[3], uS + AT_QL + aoff);
#pragma unroll
        for (int g = 0; g < 8; g++) {
            int n0 = nhalf + g * 16;
            uint32_t boff = (uint32_t)((n0 + (lane & 15)) * AT_KPITCH + ks * 16) * 2
                            + ((lane >> 4) << 4);
            uint32_t r0, r1, r2, r3;
            // non-trans ldmatrix on [n][k] rows == B-frag; pair {r0,r2},{r1,r3}
            ldsm_x4(r0, r1, r2, r3, uS + AT_KH + boff);
            uint32_t bh0[2] = {r0, r2}, bh1[2] = {r1, r3};
            ldsm_x4(r0, r1, r2, r3, uS + AT_KL + boff);
            uint32_t bl0[2] = {r0, r2}, bl1[2] = {r1, r3};
            mma_bf16(sacc[2 * g],     qh4, bh0);
            mma_bf16(sacc[2 * g],     qh4, bl0);
            mma_bf16(sacc[2 * g],     ql4, bh0);
            mma_bf16(sacc[2 * g + 1], qh4, bh1);
            mma_bf16(sacc[2 * g + 1], qh4, bl1);
            mma_bf16(sacc[2 * g + 1], ql4, bh1);
        }
    }

    // ---- mask predicates (scale-dependent bits, computed once) ------------
    int r0l = lane >> 2;           // 0..7
    int mcolB = nhalf + (lane & 3) * 2;
    unsigned long long okb[4] = {0ull, 0ull, 0ull, 0ull};
#pragma unroll
    for (int t = 0; t < 16; t++) {
        int mcol = mcolB + t * 8;
#pragma unroll
        for (int rh = 0; rh < 2; rh++) {
            int nr = qbase + band + r0l + rh * 8;
            int2 pm = *(const int2*)&mask[(size_t)(b * 256 + nr) * 256 + mcol];
            float d0 = 0.f, d1 = 0.f;
            if (nr > 0 && mcol > 0)
                d0 = dist[(size_t)(b * 255 + nr - 1) * 255 + (mcol - 1)];
            if (nr > 0)
                d1 = dist[(size_t)(b * 255 + nr - 1) * 255 + mcol];
            bool sup0 = (nr == 0) || (mcol == 0);
            bool sup1 = (nr == 0);
            int bit = t * 4 + rh * 2;
#pragma unroll
            for (int k = 0; k < 4; k++) {
                bool o0 = pm.x && (sup0 || d0 < bar[k]);
                bool o1 = pm.y && (sup1 || d1 < bar[k]);
                okb[k] |= ((unsigned long long)o0 << bit)
                        | ((unsigned long long)o1 << (bit + 1));
            }
        }
    }

    float oacc[4][2][4];
#pragma unroll
    for (int k = 0; k < 4; k++)
#pragma unroll
        for (int nt = 0; nt < 2; nt++)
#pragma unroll
            for (int j = 0; j < 4; j++) oacc[k][nt][j] = 0.f;

    int mb = band;                 // PV phase row band (same bands)
    int d0off = (warp >> 2) * 16;  // PV phase dim half

    for (int k = 0; k < 4; k++) {
        // bias prefetch (64 floats)
        float2 bv[16][2];
        const float* bp = attn_bias + (size_t)((b * 4 + k) * 256) * 256;
#pragma unroll
        for (int t = 0; t < 16; t++) {
            int mcol = mcolB + t * 8;
#pragma unroll
            for (int rh = 0; rh < 2; rh++) {
                int nr = qbase + band + r0l + rh * 8;
                bv[t][rh] = *(const float2*)&bp[(size_t)nr * 256 + mcol];
            }
        }

        // pass 1: row max
        float mx0 = -3.4e38f, mx1 = -3.4e38f;
#pragma unroll
        for (int t = 0; t < 16; t++) {
            int bit = t * 4;
            float v00 = ((okb[k] >> (bit + 0)) & 1ull) ? sacc[t][0] + bv[t][0].x : -1e12f;
            float v01 = ((okb[k] >> (bit + 1)) & 1ull) ? sacc[t][1] + bv[t][0].y : -1e12f;
            float v10 = ((okb[k] >> (bit + 2)) & 1ull) ? sacc[t][2] + bv[t][1].x : -1e12f;
            float v11 = ((okb[k] >> (bit + 3)) & 1ull) ? sacc[t][3] + bv[t][1].y : -1e12f;
            mx0 = fmaxf(mx0, fmaxf(v00, v01));
            mx1 = fmaxf(mx1, fmaxf(v10, v11));
        }
        mx0 = fmaxf(mx0, __shfl_xor_sync(0xffffffffu, mx0, 1));
        mx0 = fmaxf(mx0, __shfl_xor_sync(0xffffffffu, mx0, 2));
        mx1 = fmaxf(mx1, __shfl_xor_sync(0xffffffffu, mx1, 1));
        mx1 = fmaxf(mx1, __shfl_xor_sync(0xffffffffu, mx1, 2));
        if ((lane & 3) == 0) {
            statf[(warp >> 2) * 64 + band + r0l] = mx0;
            statf[(warp >> 2) * 64 + band + r0l + 8] = mx1;
        }
        __syncthreads();
        float gm0 = fmaxf(statf[band + r0l], statf[64 + band + r0l]);
        float gm1 = fmaxf(statf[band + r0l + 8], statf[64 + band + r0l + 8]);

        // pass 2: exp, row sum, split-store P (unnormalized)
        float s0 = 0.f, s1 = 0.f;
        int row0 = band + r0l;
#pragma unroll
        for (int t = 0; t < 16; t++) {
            int bit = t * 4;
            int mcol = mcolB + t * 8;
            float v00 = ((okb[k] >> (bit + 0)) & 1ull) ? sacc[t][0] + bv[t][0].x : -1e12f;
            float v01 = ((okb[k] >> (bit + 1)) & 1ull) ? sacc[t][1] + bv[t][0].y : -1e12f;
            float v10 = ((okb[k] >> (bit + 2)) & 1ull) ? sacc[t][2] + bv[t][1].x : -1e12f;
            float v11 = ((okb[k] >> (bit + 3)) & 1ull) ? sacc[t][3] + bv[t][1].y : -1e12f;
            float e00 = __expf(v00 - gm0);
            float e01 = __expf(v01 - gm0);
            float e10 = __expf(v10 - gm1);
            float e11 = __expf(v11 - gm1);
            s0 += e00 + e01;
            s1 += e10 + e11;
            uint32_t hp, lp;
            split2(e00, e01, hp, lp);
            *(uint32_t*)(smem + AT_PH + (row0 * AT_PPITCH + mcol) * 2) = hp;
            *(uint32_t*)(smem + AT_PL + (row0 * AT_PPITCH + mcol) * 2) = lp;
            split2(e10, e11, hp, lp);
            *(uint32_t*)(smem + AT_PH + ((row0 + 8) * AT_PPITCH + mcol) * 2) = hp;
            *(uint32_t*)(smem + AT_PL + ((row0 + 8) * AT_PPITCH + mcol) * 2) = lp;
        }
        s0 += __shfl_xor_sync(0xffffffffu, s0, 1);
        s0 += __shfl_xor_sync(0xffffffffu, s0, 2);
        s1 += __shfl_xor_sync(0xffffffffu, s1, 1);
        s1 += __shfl_xor_sync(0xffffffffu, s1, 2);
        if ((lane & 3) == 0) {
            rsumf[(k * 2 + (warp >> 2)) * 64 + band + r0l] = s0;
            rsumf[(k * 2 + (warp >> 2)) * 64 + band + r0l + 8] = s1;
        }
        __syncthreads();   // P + rsum ready

        // ---- O_k += P.V (bf16x3), warp tile 16 q x 16 dims ---------------
#pragma unroll
        for (int ks16 = 0; ks16 < 16; ks16++) {
            uint32_t ph4[4], pl4[4];
            uint32_t aoff = (uint32_t)((mb + (lane & 15)) * AT_PPITCH + ks16 * 16) * 2
                            + ((lane >> 4) << 4);
            ldsm_x4(ph4[0], ph4[1], ph4[2], ph4[3], uS + AT_PH + aoff);
            ldsm_x4(pl4[0], pl4[1], pl4[2], pl4[3], uS + AT_PL + aoff);
            uint32_t boff = (uint32_t)((ks16 * 16 + (lane & 15)) * AT_KPITCH + d0off) * 2
                            + ((lane >> 4) << 4);
            uint32_t r0, r1, r2, r3;
            ldsm_x4_t(r0, r1, r2, r3, uS + AT_VH + boff);
            uint32_t vh0[2] = {r0, r1}, vh1[2] = {r2, r3};
            ldsm_x4_t(r0, r1, r2, r3, uS + AT_VL + boff);
            uint32_t vl0[2] = {r0, r1}, vl1[2] = {r2, r3};
            mma_bf16(oacc[k][0], ph4, vh0);
            mma_bf16(oacc[k][0], ph4, vl0);
            mma_bf16(oacc[k][0], pl4, vh0);
            mma_bf16(oacc[k][1], ph4, vh1);
            mma_bf16(oacc[k][1], ph4, vl1);
            mma_bf16(oacc[k][1], pl4, vh1);
        }
        // next scale's P store happens only after the next pass-1 sync,
        // which all warps reach after finishing this PV phase.
    }

    // ---- epilogue: normalize + torch-faithful scatter ---------------------
#pragma unroll
    for (int k = 0; k < 4; k++) {
        int rl0 = mb + r0l;
        float inv0 = 1.f / (rsumf[(k * 2) * 64 + rl0] + rsumf[(k * 2 + 1) * 64 + rl0]);
        float inv1 = 1.f / (rsumf[(k * 2) * 64 + rl0 + 8] + rsumf[(k * 2 + 1) * 64 + rl0 + 8]);
#pragma unroll
        for (int nt = 0; nt < 2; nt++) {
#pragma unroll
            for (int c = 0; c < 4; c++) {
                int rloc = rl0 + (c >> 1) * 8;
                int d = d0off + nt * 8 + (lane & 3) * 2 + (c & 1);
                int n_global = qbase + rloc;
                int npr = (k * 16 + h) * 4 + (d >> 3);
                int cidx = (d & 7) * 256 + n_global;
                float val = oacc[k][nt][c] * ((c >> 1) ? inv1 : inv0);
                msg[(size_t)(b * 256 + npr) * 2048 + cidx] = val;
            }
        }
    }
}

// ------------------- fused residual + LayerNorm ----------------------------
__global__ __launch_bounds__(256) void add_ln_kernel(
    const float* __restrict__ a, const float* __restrict__ r,
    const float* __restrict__ g, const float* __restrict__ be,
    float* __restrict__ out)
{
    int row = blockIdx.x;
    int tid = threadIdx.x;
    int lane = tid & 31;
    int warp = tid >> 5;

    const float* ar = a + (size_t)row * 512;
    const float* rr = r + (size_t)row * 512;
    float v0 = ar[tid] + rr[tid];
    float v1 = ar[tid + 256] + rr[tid + 256];

    __shared__ float red[8];
    __shared__ float sMean, sRstd;

    float s = v0 + v1;
#pragma unroll
    for (int o = 16; o > 0; o >>= 1) s += __shfl_xor_sync(0xffffffffu, s, o);
    if (lane == 0) red[warp] = s;
    __syncthreads();
    if (tid == 0) {
        float t = 0.f;
#pragma unroll
        for (int i = 0; i < 8; i++) t += red[i];
        sMean = t * (1.f / 512.f);
    }
    __syncthreads();
    float mean = sMean;
    float d0 = v0 - mean;
    float d1 = v1 - mean;
    float q = d0 * d0 + d1 * d1;
#pragma unroll
    for (int o = 16; o > 0; o >>= 1) q += __shfl_xor_sync(0xffffffffu, q, o);
    if (lane == 0) red[warp] = q;
    __syncthreads();
    if (tid == 0) {
        float t = 0.f;
#pragma unroll
        for (int i = 0; i < 8; i++) t += red[i];
        sRstd = rsqrtf(t * (1.f / 512.f) + 1e-6f);
    }
    __syncthreads();
    float rstd = sRstd;
    out[(size_t)row * 512 + tid] = d0 * rstd * g[tid] + be[tid];
    out[(size_t)row * 512 + tid + 256] = d1 * rstd * g[tid + 256] + be[tid + 256];
}

// ------------------- launch ------------------------------------------------
extern "C" void kernel_launch(void* const* d_in, const int* in_sizes, int n_in,
                              void* d_out, int out_size)
{
    int base = (n_in >= 24) ? 6 : 5;

    const float* x         = (const float*)d_in[0];
    const float* dist      = (const float*)d_in[1];
    const float* dist_bar  = (const float*)d_in[2];
    const float* attn_bias = (const float*)d_in[3];
    const int*   mask      = (const int*)d_in[4];
    const float* Wq  = (const float*)d_in[base + 0];
    const float* bq  = (const float*)d_in[base + 1];
    const float* Wk  = (const float*)d_in[base + 2];
    const float* bk  = (const float*)d_in[base + 3];
    const float* Wv  = (const float*)d_in[base + 4];
    const float* bv  = (const float*)d_in[base + 5];
    const float* W1  = (const float*)d_in[base + 6];
    const float* b1  = (const float*)d_in[base + 7];
    const float* W2  = (const float*)d_in[base + 8];
    const float* b2  = (const float*)d_in[base + 9];
    const float* g1  = (const float*)d_in[base + 10];
    const float* be1 = (const float*)d_in[base + 11];
    const float* Wf1 = (const float*)d_in[base + 12];
    const float* bf1 = (const float*)d_in[base + 13];
    const float* Wf2 = (const float*)d_in[base + 14];
    const float* bf2 = (const float*)d_in[base + 15];
    const float* g2  = (const float*)d_in[base + 16];
    const float* be2 = (const float*)d_in[base + 17];
    float* out = (float*)d_out;

    float *qb, *kb, *vb, *msgb, *t1, *t2, *yb, *t3, *t4;
    cudaGetSymbolAddress((void**)&qb, g_q);
    cudaGetSymbolAddress((void**)&kb, g_k);
    cudaGetSymbolAddress((void**)&vb, g_v);
    cudaGetSymbolAddress((void**)&msgb, g_msg);
    cudaGetSymbolAddress((void**)&t1, g_t1);
    cudaGetSymbolAddress((void**)&t2, g_t2);
    cudaGetSymbolAddress((void**)&yb, g_y);
    cudaGetSymbolAddress((void**)&t3, g_t3);
    cudaGetSymbolAddress((void**)&t4, g_t4);

    cudaFuncSetAttribute(attn_mma_kernel,
                         cudaFuncAttributeMaxDynamicSharedMemorySize, ATTN_SMEM);
    cudaFuncSetAttribute(tc_gemm<0>,
                         cudaFuncAttributeMaxDynamicSharedMemorySize, GEMM_SMEM);
    cudaFuncSetAttribute(tc_gemm<1>,
                         cudaFuncAttributeMaxDynamicSharedMemorySize, GEMM_SMEM);
    cudaFuncSetAttribute(tc_gemm<2>,
                         cudaFuncAttributeMaxDynamicSharedMemorySize, GEMM_SMEM);
    cudaFuncSetAttribute(tc_qkv,
                         cudaFuncAttributeMaxDynamicSharedMemorySize, GEMM_SMEM);

    dim3 blk(256);
    dim3 gQKV(D_ / 64, BN_ / 64, 3);
    dim3 gD(D_ / 64, BN_ / 64);
    dim3 gF(FFN_ / 64, BN_ / 64);
    dim3 gAttn(B_ * H_, 4);

    tc_qkv<<<gQKV, blk, GEMM_SMEM>>>(x, Wq, bq, Wk, bk, Wv, bv, qb, kb, vb);

    attn_mma_kernel<<<gAttn, blk, ATTN_SMEM>>>(qb, kb, vb, attn_bias, mask,
                                               dist, dist_bar, msgb);

    tc_gemm<1><<<gD, blk, GEMM_SMEM>>>(msgb, W1, b1, t1, D_, KD_);
    tc_gemm<0><<<gD, blk, GEMM_SMEM>>>(t1, W2, b2, t2, D_, D_);
    add_ln_kernel<<<BN_, blk>>>(t2, x, g1, be1, yb);

    tc_gemm<2><<<gF, blk, GEMM_SMEM>>>(yb, Wf1, bf1, t3, FFN_, D_);
    tc_gemm<0><<<gD, blk, GEMM_SMEM>>>(t3, Wf2, bf2, t4, D_, FFN_);
    add_ln_kernel<<<BN_, blk>>>(t4, yb, g2, be2, out);
}